// round 1
// baseline (speedup 1.0000x reference)
#include <cuda_runtime.h>
#include <cstddef>

// out[b,i,j] = W[words[b,i], words[b,j]]  (+ root[words[b,i]] when i==j)
// V=10000, B=8, N=2048
// Strategy: one CTA per (b,i). Stream the full 40KB W row into shared memory
// with coalesced float4 loads (perfect MLP), then gather the 2048 needed
// columns from smem and store coalesced float4s.

#define V 10000
#define B_DIM 8
#define N_DIM 2048
#define THREADS 256

__global__ __launch_bounds__(THREADS) void pair_gather_kernel(
    const int* __restrict__ words,
    const float* __restrict__ W,
    const float* __restrict__ root,
    float* __restrict__ out)
{
    __shared__ alignas(16) float srow[V];     // 40000 B
    __shared__ int scols[N_DIM];              // 8192 B   (total 48192 B < 48KB)

    const int blk = blockIdx.x;               // blk = b*N + i
    const int b   = blk >> 11;                // / 2048
    const int i   = blk & (N_DIM - 1);        // % 2048
    const int t   = threadIdx.x;

    const int* __restrict__ wb = words + (size_t)b * N_DIM;

    // cache the column index list for this batch
    #pragma unroll
    for (int j = t; j < N_DIM; j += THREADS)
        scols[j] = __ldg(wb + j);

    const int r = __ldg(wb + i);

    // stream W row r into smem: 10000 floats = 2500 float4 (exact)
    const float4* __restrict__ Wr = reinterpret_cast<const float4*>(W + (size_t)r * V);
    float4* srow4 = reinterpret_cast<float4*>(srow);
    for (int k = t; k < V / 4; k += THREADS)
        srow4[k] = __ldg(Wr + k);

    const float rootv = __ldg(root + r);

    __syncthreads();

    float* __restrict__ orow = out + (size_t)blk * N_DIM;

    // 2048 outputs: 2 iterations x 256 threads x 4 consecutive j each
    #pragma unroll
    for (int it = 0; it < 2; ++it) {
        const int j0 = (it * THREADS + t) * 4;
        float4 v;
        v.x = srow[scols[j0 + 0]];
        v.y = srow[scols[j0 + 1]];
        v.z = srow[scols[j0 + 2]];
        v.w = srow[scols[j0 + 3]];
        const unsigned d = (unsigned)(i - j0);
        if (d < 4u) {
            if      (d == 0u) v.x += rootv;
            else if (d == 1u) v.y += rootv;
            else if (d == 2u) v.z += rootv;
            else              v.w += rootv;
        }
        *reinterpret_cast<float4*>(orow + j0) = v;
    }
}

extern "C" void kernel_launch(void* const* d_in, const int* in_sizes, int n_in,
                              void* d_out, int out_size)
{
    const int*   words = (const int*)  d_in[0];
    const float* W     = (const float*)d_in[1];
    const float* root  = (const float*)d_in[2];
    float*       out   = (float*)d_out;

    pair_gather_kernel<<<B_DIM * N_DIM, THREADS>>>(words, W, root, out);
}

// round 2
// speedup vs baseline: 1.5198x; 1.5198x over previous
#include <cuda_runtime.h>
#include <cstddef>

// out[b,i,j] = W[words[b,i], words[b,j]]  (+ root[words[b,i]] when i==j)
// V=10000, B=8, N=2048.
//
// R2: group (b,i) pairs by row id r = words[b,i] via a counting-sort
// pre-pass, then one CTA per distinct r loads the 40KB W row ONCE and emits
// every output row that needs it. Distinct rows ~8058 of 16384 -> halves
// DRAM read traffic, and consecutive CTAs stream consecutive W rows.

#define V 10000
#define B_DIM 8
#define N_DIM 2048
#define NITEMS (B_DIM * N_DIM)   // 16384
#define THREADS 256
#define SCAN_T 512
#define BINS_PER_T 20            // 512*20 = 10240 >= V+1

__device__ int d_count[V];
__device__ int d_offset[V + 1];
__device__ int d_cursor[V];
__device__ int d_items[NITEMS];

// ---- pre-pass ----
__global__ void zero_counts_kernel() {
    int t = blockIdx.x * blockDim.x + threadIdx.x;
    if (t < V) d_count[t] = 0;
}

__global__ void count_kernel(const int* __restrict__ words) {
    int blk = blockIdx.x * blockDim.x + threadIdx.x;
    if (blk < NITEMS) atomicAdd(&d_count[words[blk]], 1);
}

__global__ __launch_bounds__(SCAN_T) void scan_kernel() {
    __shared__ int partial[SCAN_T];
    const int t = threadIdx.x;
    const int base = t * BINS_PER_T;

    int local[BINS_PER_T];
    int s = 0;
    #pragma unroll
    for (int k = 0; k < BINS_PER_T; ++k) {
        int idx = base + k;
        local[k] = s;
        s += (idx < V) ? d_count[idx] : 0;
    }
    partial[t] = s;
    __syncthreads();

    // inclusive Hillis-Steele scan of per-thread sums
    for (int off = 1; off < SCAN_T; off <<= 1) {
        int v = 0;
        if (t >= off) v = partial[t - off];
        __syncthreads();
        if (t >= off) partial[t] += v;
        __syncthreads();
    }
    const int excl = (t == 0) ? 0 : partial[t - 1];

    #pragma unroll
    for (int k = 0; k < BINS_PER_T; ++k) {
        int idx = base + k;
        if (idx <= V) {
            int o = excl + local[k];
            d_offset[idx] = o;
            if (idx < V) d_cursor[idx] = o;
        }
    }
}

__global__ void scatter_kernel(const int* __restrict__ words) {
    int blk = blockIdx.x * blockDim.x + threadIdx.x;
    if (blk < NITEMS) {
        int r = words[blk];
        int pos = atomicAdd(&d_cursor[r], 1);
        d_items[pos] = blk;
    }
}

// ---- main kernel: one CTA per vocab id ----
__global__ __launch_bounds__(THREADS) void pair_gather_grouped_kernel(
    const int* __restrict__ words,
    const float* __restrict__ W,
    const float* __restrict__ root,
    float* __restrict__ out)
{
    __shared__ alignas(16) float srow[V];   // 40000 B

    const int r     = blockIdx.x;
    const int begin = d_offset[r];
    const int end   = d_offset[r + 1];
    if (begin == end) return;

    const int t = threadIdx.x;

    // stream W row r into smem: 10000 floats = 2500 float4 (exact)
    const float4* __restrict__ Wr = reinterpret_cast<const float4*>(W + (size_t)r * V);
    float4* srow4 = reinterpret_cast<float4*>(srow);
    #pragma unroll 5
    for (int k = t; k < V / 4; k += THREADS)
        srow4[k] = __ldg(Wr + k);

    const float rootv = __ldg(root + r);
    __syncthreads();

    for (int it = begin; it < end; ++it) {
        const int blk = d_items[it];        // b*N + i
        const int b   = blk >> 11;
        const int i   = blk & (N_DIM - 1);
        const int* __restrict__ wb = words + (size_t)b * N_DIM;
        float* __restrict__ orow   = out + (size_t)blk * N_DIM;

        #pragma unroll
        for (int u = 0; u < 2; ++u) {
            const int j0 = (u * THREADS + t) * 4;
            const int4 c = __ldg(reinterpret_cast<const int4*>(wb + j0));
            float4 v;
            v.x = srow[c.x];
            v.y = srow[c.y];
            v.z = srow[c.z];
            v.w = srow[c.w];
            const unsigned d = (unsigned)(i - j0);
            if (d < 4u) {
                if      (d == 0u) v.x += rootv;
                else if (d == 1u) v.y += rootv;
                else if (d == 2u) v.z += rootv;
                else              v.w += rootv;
            }
            *reinterpret_cast<float4*>(orow + j0) = v;
        }
        // no sync needed: srow is read-only across items
    }
}

extern "C" void kernel_launch(void* const* d_in, const int* in_sizes, int n_in,
                              void* d_out, int out_size)
{
    const int*   words = (const int*)  d_in[0];
    const float* W     = (const float*)d_in[1];
    const float* root  = (const float*)d_in[2];
    float*       out   = (float*)d_out;

    zero_counts_kernel<<<(V + 255) / 256, 256>>>();
    count_kernel<<<(NITEMS + 255) / 256, 256>>>(words);
    scan_kernel<<<1, SCAN_T>>>();
    scatter_kernel<<<(NITEMS + 255) / 256, 256>>>(words);
    pair_gather_grouped_kernel<<<V, THREADS>>>(words, W, root, out);
}

// round 3
// speedup vs baseline: 1.8741x; 1.2332x over previous
#include <cuda_runtime.h>
#include <cstdint>
#include <cstddef>

// out[b,i,j] = W[words[b,i], words[b,j]]  (+ root[words[b,i]] when i==j)
// V=10000, B=8, N=2048
//
// R3: persistent double-buffered CTAs. Pre-pass groups (b,i) items by row id.
// Main kernel: 296 persistent CTAs grab rows from a global cursor; each row is
// streamed into shared memory with one cp.async.bulk (TMA) while the previous
// row's outputs are being gathered+stored. Overlaps the 322MB of reads with
// the 134MB of writes.

#define V 10000
#define B_DIM 8
#define N_DIM 2048
#define NITEMS (B_DIM * N_DIM)   // 16384
#define THREADS 256
#define ROW_BYTES (V * 4)        // 40000
#define GRID_MAIN 296            // 2 CTAs per SM (148 SMs)
#define SCAN_T 512
#define BINS_PER_T 20            // 512*20 = 10240 >= V+1

__device__ int d_count[V];       // zero-initialized at module load; re-zeroed by scan
__device__ int d_offset[V + 1];
__device__ int d_pos[NITEMS];
__device__ int d_items[NITEMS];
__device__ int d_wcursor;

// ---------------- pre-pass ----------------

__global__ void count_kernel(const int* __restrict__ words) {
    int k = blockIdx.x * blockDim.x + threadIdx.x;
    if (k < NITEMS) {
        int r = words[k];
        d_pos[k] = atomicAdd(&d_count[r], 1);
    }
}

__global__ __launch_bounds__(SCAN_T) void scan_kernel() {
    __shared__ int partial[SCAN_T];
    const int t = threadIdx.x;
    const int base = t * BINS_PER_T;

    int local[BINS_PER_T];
    int s = 0;
    #pragma unroll
    for (int k = 0; k < BINS_PER_T; ++k) {
        int idx = base + k;
        local[k] = s;
        s += (idx < V) ? d_count[idx] : 0;
    }
    partial[t] = s;
    __syncthreads();

    for (int off = 1; off < SCAN_T; off <<= 1) {
        int v = 0;
        if (t >= off) v = partial[t - off];
        __syncthreads();
        if (t >= off) partial[t] += v;
        __syncthreads();
    }
    const int excl = (t == 0) ? 0 : partial[t - 1];

    #pragma unroll
    for (int k = 0; k < BINS_PER_T; ++k) {
        int idx = base + k;
        if (idx <= V) {
            d_offset[idx] = excl + local[k];
            if (idx < V) d_count[idx] = 0;   // re-zero for next graph replay
        }
    }
    if (t == 0) d_wcursor = 0;               // reset work cursor
}

__global__ void place_kernel(const int* __restrict__ words) {
    int k = blockIdx.x * blockDim.x + threadIdx.x;
    if (k < NITEMS) {
        d_items[d_offset[words[k]] + d_pos[k]] = k;
    }
}

// ---------------- main kernel helpers ----------------

__device__ __forceinline__ void mbar_init(uint32_t mbar, uint32_t count) {
    asm volatile("mbarrier.init.shared.b64 [%0], %1;" :: "r"(mbar), "r"(count) : "memory");
}
__device__ __forceinline__ void mbar_expect_tx(uint32_t mbar, uint32_t bytes) {
    asm volatile("mbarrier.arrive.expect_tx.shared.b64 _, [%0], %1;"
                 :: "r"(mbar), "r"(bytes) : "memory");
}
__device__ __forceinline__ void bulk_copy_g2s(uint32_t dst_smem, const void* src,
                                              uint32_t bytes, uint32_t mbar) {
    asm volatile("cp.async.bulk.shared::cta.global.mbarrier::complete_tx::bytes "
                 "[%0], [%1], %2, [%3];"
                 :: "r"(dst_smem), "l"(src), "r"(bytes), "r"(mbar) : "memory");
}
__device__ __forceinline__ void mbar_wait(uint32_t mbar, uint32_t phase) {
    asm volatile(
        "{\n\t"
        ".reg .pred P;\n\t"
        "WAIT_%=:\n\t"
        "mbarrier.try_wait.parity.acquire.cta.shared::cta.b64 P, [%0], %1, 0x989680;\n\t"
        "@P bra DONE_%=;\n\t"
        "bra WAIT_%=;\n\t"
        "DONE_%=:\n\t"
        "}"
        :: "r"(mbar), "r"(phase) : "memory");
}

// ---------------- main kernel ----------------

__global__ __launch_bounds__(THREADS) void pair_gather_persistent_kernel(
    const int* __restrict__ words,
    const float* __restrict__ W,
    const float* __restrict__ root,
    float* __restrict__ out)
{
    extern __shared__ float sbuf[];   // [2*V floats][2 mbarriers]
    __shared__ int s_r, s_b, s_e;

    const int t = threadIdx.x;
    const uint32_t smem_base = (uint32_t)__cvta_generic_to_shared(sbuf);
    const uint32_t mbar0 = smem_base + 2 * ROW_BYTES;       // 80000, 8-aligned
    float* buf[2] = { sbuf, sbuf + V };

    if (t == 0) {
        mbar_init(mbar0, 1);
        mbar_init(mbar0 + 8, 1);
        asm volatile("fence.proxy.async.shared::cta;" ::: "memory");
    }
    __syncthreads();

    // collective row grab: returns row id (or -1) + item range, broadcast
    auto grab = [&](int& rr, int& rb, int& re) {
        if (t == 0) {
            int r, b = 0, e = 0;
            for (;;) {
                r = atomicAdd(&d_wcursor, 1);
                if (r >= V) { r = -1; break; }
                b = d_offset[r]; e = d_offset[r + 1];
                if (b != e) break;
            }
            s_r = r; s_b = b; s_e = e;
        }
        __syncthreads();
        rr = s_r; rb = s_b; re = s_e;
        __syncthreads();    // everyone has read s_* before next grab overwrites
    };

    auto issue = [&](int slot, int r) {
        if (t == 0) {
            uint32_t mb = mbar0 + slot * 8;
            mbar_expect_tx(mb, ROW_BYTES);
            bulk_copy_g2s(smem_base + slot * ROW_BYTES,
                          W + (size_t)r * V, ROW_BYTES, mb);
        }
    };

    int rc, cb, ce;                 // current row
    int rn, nb, ne;                 // next row
    unsigned phase[2] = {0u, 0u};

    grab(rc, cb, ce);
    if (rc >= 0) issue(0, rc);
    grab(rn, nb, ne);
    if (rn >= 0) issue(1, rn);

    int cur = 0;
    while (rc >= 0) {
        mbar_wait(mbar0 + cur * 8, phase[cur]);
        phase[cur] ^= 1u;

        const float* __restrict__ row = buf[cur];
        const float rootv = __ldg(root + rc);

        for (int it = cb; it < ce; ++it) {
            const int blk = d_items[it];          // b*N + i
            const int b   = blk >> 11;
            const int i   = blk & (N_DIM - 1);
            const int4* __restrict__ wb4 =
                reinterpret_cast<const int4*>(words + (size_t)b * N_DIM);
            float* __restrict__ orow = out + (size_t)blk * N_DIM;

            #pragma unroll
            for (int u = 0; u < 2; ++u) {
                const int j0 = (u * THREADS + t) * 4;
                const int4 c = __ldg(wb4 + (j0 >> 2));
                float4 v;
                v.x = row[c.x];
                v.y = row[c.y];
                v.z = row[c.z];
                v.w = row[c.w];
                const unsigned d = (unsigned)(i - j0);
                if (d < 4u) {
                    if      (d == 0u) v.x += rootv;
                    else if (d == 1u) v.y += rootv;
                    else if (d == 2u) v.z += rootv;
                    else              v.w += rootv;
                }
                *reinterpret_cast<float4*>(orow + j0) = v;
            }
        }

        // grab next-next row; its barrier guarantees all threads finished
        // reading buf[cur] before we overwrite it with a new TMA load
        int r2, b2, e2;
        grab(r2, b2, e2);
        if (r2 >= 0) issue(cur, r2);

        rc = rn; cb = nb; ce = ne;
        rn = r2; nb = b2; ne = e2;
        cur ^= 1;
    }
}

// ---------------- launch ----------------

extern "C" void kernel_launch(void* const* d_in, const int* in_sizes, int n_in,
                              void* d_out, int out_size)
{
    const int*   words = (const int*)  d_in[0];
    const float* W     = (const float*)d_in[1];
    const float* root  = (const float*)d_in[2];
    float*       out   = (float*)d_out;

    static const size_t SMEM_DYN = 2 * ROW_BYTES + 32;  // 2 bufs + mbarriers
    cudaFuncSetAttribute(pair_gather_persistent_kernel,
                         cudaFuncAttributeMaxDynamicSharedMemorySize,
                         (int)SMEM_DYN);

    count_kernel<<<(NITEMS + 255) / 256, 256>>>(words);
    scan_kernel<<<1, SCAN_T>>>();
    place_kernel<<<(NITEMS + 255) / 256, 256>>>(words);
    pair_gather_persistent_kernel<<<GRID_MAIN, THREADS, SMEM_DYN>>>(words, W, root, out);
}